// round 13
// baseline (speedup 1.0000x reference)
#include <cuda_runtime.h>
#include <math.h>

// Problem constants (fixed shapes from reference)
#define NQ      262144      // total queries = B*L*cg = 4*1024*64
#define NSAM    1024        // prior samples
#define THREADS 448
#define QPT     4           // queries per WARP-PAIR thread (2 f32x2 lane-packs)
#define CHUNK   16          // samples per argmax chunk
#define NCHUNK  (NSAM / CHUNK)          // 64 total
#define CH_PER_THREAD (NCHUNK / 2)      // 32 per thread (warp-pair split)
#define PAIRS_PER_BLOCK (THREADS / 64)  // 7 warp-pairs per block
#define ZHAT_OFF   0
#define NOQ_OFF    1048576  // B*L*C
#define IDX_OFF    2097152  // 2*B*L*C
#define FULL_OUT   2359296  // + B*L*cg

// Constant-space sample table: warp-uniform loads -> LDCU/UR candidates
__constant__ float4 cprior[NSAM];      // 16 KB

// ---- packed f32x2 helpers (Blackwell FFMA2/FMUL2) ----
__device__ __forceinline__ unsigned long long ffma2(unsigned long long a,
                                                    unsigned long long b,
                                                    unsigned long long c) {
    unsigned long long d;
    asm("fma.rn.f32x2 %0, %1, %2, %3;" : "=l"(d) : "l"(a), "l"(b), "l"(c));
    return d;
}
__device__ __forceinline__ unsigned long long fmul2(unsigned long long a,
                                                    unsigned long long b) {
    unsigned long long d;
    asm("mul.rn.f32x2 %0, %1, %2;" : "=l"(d) : "l"(a), "l"(b));
    return d;
}
__device__ __forceinline__ unsigned long long pack2(float x) {     // (x, x)
    unsigned long long r;
    asm("mov.b64 %0, {%1, %1};" : "=l"(r) : "f"(x));
    return r;
}
__device__ __forceinline__ unsigned long long packxy(float lo, float hi) {  // (lo, hi)
    unsigned long long r;
    asm("mov.b64 %0, {%1, %2};" : "=l"(r) : "f"(lo), "f"(hi));
    return r;
}
__device__ __forceinline__ float lo2(unsigned long long a) {
    return __uint_as_float((unsigned)(a & 0xffffffffull));
}
__device__ __forceinline__ float hi2(unsigned long long a) {
    return __uint_as_float((unsigned)(a >> 32));
}

// Packed score of TWO queries (in lanes) against ONE sample.
// Main loop (constant src) and rescan (smem src) share this sequence and the
// same underlying bytes -> bit-identical recompute.
__device__ __forceinline__ unsigned long long score2(
        const unsigned long long* u, const unsigned long long* vh,
        unsigned long long s0, unsigned long long s1,
        unsigned long long s2, unsigned long long s3) {
    unsigned long long t, a;
    t = ffma2(vh[0], s0, u[0]);  a = fmul2(s0, t);
    t = ffma2(vh[1], s1, u[1]);  a = ffma2(s1, t, a);
    t = ffma2(vh[2], s2, u[2]);  a = ffma2(s2, t, a);
    t = ffma2(vh[3], s3, u[3]);  a = ffma2(s3, t, a);
    return a;
}

// Recompute one chunk for one lane-pack from the smem copy; return smallest
// sample index whose selected lane equals target exactly.
__device__ __forceinline__ int rescan_chunk(const float4* __restrict__ tab,
                                            const unsigned long long* u,
                                            const unsigned long long* vh,
                                            int chunk, float target, int odd) {
    int found = NSAM;
    #pragma unroll 4
    for (int t = 0; t < CHUNK; t++) {
        int n = chunk * CHUNK + t;
        float4 s = tab[n];
        unsigned long long a = score2(u, vh, pack2(s.x), pack2(s.y),
                                             pack2(s.z), pack2(s.w));
        float v = odd ? hi2(a) : lo2(a);
        if (v == target) found = min(found, n);
    }
    return found;
}

__global__ void __launch_bounds__(THREADS, 2)
gq_kernel(const float* __restrict__ z,
          const float* __restrict__ eps,
          const float* __restrict__ prior,
          float* __restrict__ out,
          int out_size)
{
    __shared__ __align__(16) float4 tab[NSAM];        // rescan/gather copy, 16 KB
    __shared__ float mbuf[THREADS * 4];               // merge: maxes
    __shared__ int   cbuf[THREADS * 4];               // merge: chunk ids
    __shared__ int   rbuf[THREADS * 2];               // rescan result exchange

    const int tid  = threadIdx.x;
    const int wid  = tid >> 5;
    const int lane = tid & 31;
    const int h    = wid & 1;          // which sample half this WARP scans

    for (int n = tid; n < NSAM; n += THREADS)
        tab[n] = reinterpret_cast<const float4*>(prior)[n];

    // Warp pair (2w, 2w+1) owns 32 query-quads; thread = one quad.
    const int pairg = blockIdx.x * PAIRS_PER_BLOCK + (wid >> 1);
    const int quad  = pairg * 32 + lane;
    const bool valid = (quad < NQ / QPT);
    const int kq = valid ? quad : (NQ / QPT - 1);     // clamp for safe loads
    const int k0 = kq * QPT;
    const int bl = k0 >> 6;     // (b*L + l)
    const int j  = k0 & 63;

    // Lane-packed per-query coefficients (identical in both warps of a pair)
    unsigned long long u01[4], u23[4], vh01[4], vh23[4];

    #pragma unroll
    for (int g = 0; g < 4; g++) {
        const int moff = bl * 512 + g * 64 + j;           // mu
        float4 mu4 = *reinterpret_cast<const float4*>(z + moff);
        float4 lv4 = *reinterpret_cast<const float4*>(z + moff + 256);
        lv4.x = fminf(fmaxf(lv4.x, -30.0f), 20.0f);
        lv4.y = fminf(fmaxf(lv4.y, -30.0f), 20.0f);
        lv4.z = fminf(fmaxf(lv4.z, -30.0f), 20.0f);
        lv4.w = fminf(fmaxf(lv4.w, -30.0f), 20.0f);
        float ivx = expf(-lv4.x), ivy = expf(-lv4.y);
        float ivz = expf(-lv4.z), ivw = expf(-lv4.w);
        u01[g]  = packxy(mu4.x * ivx, mu4.y * ivy);
        u23[g]  = packxy(mu4.z * ivz, mu4.w * ivw);
        vh01[g] = packxy(0.5f * (1.0f - ivx), 0.5f * (1.0f - ivy));
        vh23[g] = packxy(0.5f * (1.0f - ivz), 0.5f * (1.0f - ivw));

        // Fused zhat_noquant (written once per quad, by the even warp)
        if (h == 0 && valid && out_size >= IDX_OFF) {
            const int eoff = bl * 256 + g * 64 + j;
            float4 e4 = *reinterpret_cast<const float4*>(eps + eoff);
            float4 nq;
            nq.x = fmaf(e4.x, expf(0.5f * lv4.x), mu4.x);
            nq.y = fmaf(e4.y, expf(0.5f * lv4.y), mu4.y);
            nq.z = fmaf(e4.z, expf(0.5f * lv4.z), mu4.z);
            nq.w = fmaf(e4.w, expf(0.5f * lv4.w), mu4.w);
            *reinterpret_cast<float4*>(out + NOQ_OFF + eoff) = nq;
        }
    }
    __syncthreads();   // tab ready (all threads reach: no early returns)

    const float NEG_INF = -__int_as_float(0x7f800000);
    float gm[QPT];
    int   gc[QPT];
    #pragma unroll
    for (int q = 0; q < QPT; q++) { gm[q] = NEG_INF; gc[q] = 0; }

    // This warp scans chunks [h*32, h*32+32); constant-space addresses are
    // warp-uniform (h and loop counters only) -> LDCU/UR eligible.
    const int ch0 = h * CH_PER_THREAD;
    for (int ci = 0; ci < CH_PER_THREAD; ci++) {
        const int ch = ch0 + ci;
        float m0 = NEG_INF, m1 = NEG_INF, m2 = NEG_INF, m3 = NEG_INF;
        const float4* cbase = &cprior[ch * CHUNK];
        #pragma unroll
        for (int t = 0; t < CHUNK; t++) {
            float4 s = cbase[t];                       // uniform const load
            unsigned long long s0 = pack2(s.x), s1 = pack2(s.y);
            unsigned long long s2 = pack2(s.z), s3 = pack2(s.w);
            unsigned long long a01 = score2(u01, vh01, s0, s1, s2, s3);
            unsigned long long a23 = score2(u23, vh23, s0, s1, s2, s3);
            m0 = fmaxf(m0, lo2(a01));
            m1 = fmaxf(m1, hi2(a01));
            m2 = fmaxf(m2, lo2(a23));
            m3 = fmaxf(m3, hi2(a23));
        }
        // Strict '>' keeps the earliest chunk on ties (first-index semantics)
        if (m0 > gm[0]) { gm[0] = m0; gc[0] = ch; }
        if (m1 > gm[1]) { gm[1] = m1; gc[1] = ch; }
        if (m2 > gm[2]) { gm[2] = m2; gc[2] = ch; }
        if (m3 > gm[3]) { gm[3] = m3; gc[3] = ch; }
    }

    // Merge halves across the warp pair via smem (partner thread = tid ^ 32).
    #pragma unroll
    for (int q = 0; q < QPT; q++) { mbuf[tid * 4 + q] = gm[q]; cbuf[tid * 4 + q] = gc[q]; }
    __syncthreads();
    const int ptid = tid ^ 32;
    #pragma unroll
    for (int q = 0; q < QPT; q++) {
        float pm = mbuf[ptid * 4 + q];
        int   pc = cbuf[ptid * 4 + q];
        // On equal max, smaller chunk id wins -> global first-index semantics
        if (pm > gm[q] || (pm == gm[q] && pc < gc[q])) { gm[q] = pm; gc[q] = pc; }
    }

    // Parallel rescan: even warp resolves q0,q1; odd warp q2,q3 (coefficients
    // bit-identical in both). SEL-based operand pick, smem table source.
    unsigned long long ua[4], va[4];
    #pragma unroll
    for (int g = 0; g < 4; g++) {
        ua[g] = h ? u23[g]  : u01[g];
        va[g] = h ? vh23[g] : vh01[g];
    }
    const int   ca0 = h ? gc[2] : gc[0];
    const int   ca1 = h ? gc[3] : gc[1];
    const float ta0 = h ? gm[2] : gm[0];
    const float ta1 = h ? gm[3] : gm[1];
    int ra = rescan_chunk(tab, ua, va, ca0, ta0, 0);
    int rb = rescan_chunk(tab, ua, va, ca1, ta1, 1);

    rbuf[tid * 2]     = ra;
    rbuf[tid * 2 + 1] = rb;
    __syncthreads();

    if (h != 0 || !valid) return;   // all barriers done; safe to exit

    int bidx[QPT];
    bidx[0] = ra;
    bidx[1] = rb;
    bidx[2] = rbuf[ptid * 2];
    bidx[3] = rbuf[ptid * 2 + 1];

    {
        // Gather winning prior rows from the smem table
        float r[QPT][4];
        #pragma unroll
        for (int q = 0; q < QPT; q++) {
            float4 s = tab[bidx[q]];
            r[q][0] = s.x; r[q][1] = s.y; r[q][2] = s.z; r[q][3] = s.w;
        }
        const int obase = bl * 256 + j;
        #pragma unroll
        for (int g = 0; g < 4; g++) {
            float4 o4 = make_float4(r[0][g], r[1][g], r[2][g], r[3][g]);
            *reinterpret_cast<float4*>(out + ZHAT_OFF + obase + g * 64) = o4;
        }
        if (out_size >= FULL_OUT) {
            float4 i4 = make_float4((float)bidx[0], (float)bidx[1],
                                    (float)bidx[2], (float)bidx[3]);
            *reinterpret_cast<float4*>(out + IDX_OFF + k0) = i4;
        }
    }
}

extern "C" void kernel_launch(void* const* d_in, const int* in_sizes, int n_in,
                              void* d_out, int out_size) {
    const float* z     = (const float*)d_in[0];
    const float* eps   = (const float*)d_in[1];
    const float* prior = (const float*)d_in[2];
    (void)in_sizes; (void)n_in;

    // Stage prior into constant memory (graph-capturable async D2D copy)
    cudaMemcpyToSymbolAsync(cprior, prior, NSAM * sizeof(float4), 0,
                            cudaMemcpyDeviceToDevice, 0);

    const int pairs  = NQ / QPT / 32;                      // 2048 warp-pairs
    const int blocks = (pairs + PAIRS_PER_BLOCK - 1) / PAIRS_PER_BLOCK;  // 293
    gq_kernel<<<blocks, THREADS>>>(z, eps, prior, (float*)d_out, out_size);
}

// round 15
// speedup vs baseline: 1.0208x; 1.0208x over previous
#include <cuda_runtime.h>
#include <math.h>

// Problem constants (fixed shapes from reference)
#define NQ      262144      // total queries = B*L*cg = 4*1024*64
#define NSAM    1024        // prior samples
#define THREADS 448
#define QPT     2           // queries per thread-PAIR (1 f32x2 lane-pack)
#define SPLIT   2           // threads per query-pair (each scans NSAM/SPLIT samples)
#define CHUNK   16          // samples per argmax chunk
#define NCHUNK  (NSAM / CHUNK)          // 64 total
#define CH_PER_THREAD (NCHUNK / SPLIT)  // 32 per thread
#define ZHAT_OFF   0
#define NOQ_OFF    1048576  // B*L*C
#define IDX_OFF    2097152  // 2*B*L*C
#define FULL_OUT   2359296  // + B*L*cg

// ---- packed f32x2 helpers (Blackwell FFMA2/FMUL2) ----
__device__ __forceinline__ unsigned long long ffma2(unsigned long long a,
                                                    unsigned long long b,
                                                    unsigned long long c) {
    unsigned long long d;
    asm("fma.rn.f32x2 %0, %1, %2, %3;" : "=l"(d) : "l"(a), "l"(b), "l"(c));
    return d;
}
__device__ __forceinline__ unsigned long long fmul2(unsigned long long a,
                                                    unsigned long long b) {
    unsigned long long d;
    asm("mul.rn.f32x2 %0, %1, %2;" : "=l"(d) : "l"(a), "l"(b));
    return d;
}
__device__ __forceinline__ unsigned long long pack2(float x) {     // (x, x)
    unsigned long long r;
    asm("mov.b64 %0, {%1, %1};" : "=l"(r) : "f"(x));
    return r;
}
__device__ __forceinline__ unsigned long long packxy(float lo, float hi) {  // (lo, hi)
    unsigned long long r;
    asm("mov.b64 %0, {%1, %2};" : "=l"(r) : "f"(lo), "f"(hi));
    return r;
}
__device__ __forceinline__ float lo2(unsigned long long a) {
    return __uint_as_float((unsigned)(a & 0xffffffffull));
}
__device__ __forceinline__ float hi2(unsigned long long a) {
    return __uint_as_float((unsigned)(a >> 32));
}

// Packed score of TWO queries (in lanes) against ONE sample.
// Main loop and rescan share this sequence -> bit-identical recompute.
__device__ __forceinline__ unsigned long long score2(
        const unsigned long long* u, const unsigned long long* vh,
        unsigned long long s0, unsigned long long s1,
        unsigned long long s2, unsigned long long s3) {
    unsigned long long t, a;
    t = ffma2(vh[0], s0, u[0]);  a = fmul2(s0, t);
    t = ffma2(vh[1], s1, u[1]);  a = ffma2(s1, t, a);
    t = ffma2(vh[2], s2, u[2]);  a = ffma2(s2, t, a);
    t = ffma2(vh[3], s3, u[3]);  a = ffma2(s3, t, a);
    return a;
}

// Recompute one chunk for the lane-pack; return smallest sample index whose
// selected lane equals target exactly.
__device__ __forceinline__ int rescan_chunk(const float4* __restrict__ tab,
                                            const unsigned long long* u,
                                            const unsigned long long* vh,
                                            int chunk, float target, int odd) {
    int found = NSAM;
    #pragma unroll 4
    for (int t = 0; t < CHUNK; t++) {
        int n = chunk * CHUNK + t;
        float4 s = tab[n];
        unsigned long long a = score2(u, vh, pack2(s.x), pack2(s.y),
                                             pack2(s.z), pack2(s.w));
        float v = odd ? hi2(a) : lo2(a);
        if (v == target) found = min(found, n);
    }
    return found;
}

__global__ void __launch_bounds__(THREADS, 4)
gq_kernel(const float* __restrict__ z,
          const float* __restrict__ eps,
          const float* __restrict__ prior,
          float* __restrict__ out,
          int out_size)
{
    // Sample table = raw prior rows: tab[n] = (S_g0, S_g1, S_g2, S_g3)
    __shared__ __align__(16) float4 tab[NSAM];     // 16384 B (x4 CTAs = 64 KB/SM)

    const int tid = threadIdx.x;
    for (int n = tid; n < NSAM; n += THREADS)
        tab[n] = reinterpret_cast<const float4*>(prior)[n];

    // Adjacent thread pair (2i, 2i+1) owns query-pair i; h = which sample half.
    const int gtid   = blockIdx.x * THREADS + tid;
    const int pairid = gtid >> 1;
    const int h      = gtid & 1;
    const int k0     = pairid * QPT;
    const bool valid = (k0 < NQ);   // boundary at gtid 262144: warp-aligned
    const int bl = k0 >> 6;     // (b*L + l)
    const int j  = k0 & 63;     // even

    // Lane-packed per-query coefficients: u[g]=(u_q0,u_q1), vh[g]=(vh_q0,vh_q1)
    unsigned long long u[4], vh[4];

    if (valid) {
        #pragma unroll
        for (int g = 0; g < 4; g++) {
            const int moff = bl * 512 + g * 64 + j;           // mu
            float2 mu2 = *reinterpret_cast<const float2*>(z + moff);
            float2 lv2 = *reinterpret_cast<const float2*>(z + moff + 256);
            lv2.x = fminf(fmaxf(lv2.x, -30.0f), 20.0f);
            lv2.y = fminf(fmaxf(lv2.y, -30.0f), 20.0f);
            float ivx = expf(-lv2.x), ivy = expf(-lv2.y);
            u[g]  = packxy(mu2.x * ivx, mu2.y * ivy);
            vh[g] = packxy(0.5f * (1.0f - ivx), 0.5f * (1.0f - ivy));

            // Fused zhat_noquant (written once per pair, by the h==0 thread)
            if (h == 0 && out_size >= IDX_OFF) {
                const int eoff = bl * 256 + g * 64 + j;
                float2 e2 = *reinterpret_cast<const float2*>(eps + eoff);
                float2 nq;
                nq.x = fmaf(e2.x, expf(0.5f * lv2.x), mu2.x);
                nq.y = fmaf(e2.y, expf(0.5f * lv2.y), mu2.y);
                *reinterpret_cast<float2*>(out + NOQ_OFF + eoff) = nq;
            }
        }
    }
    __syncthreads();
    if (!valid) return;   // whole warps exit; shuffles below stay full-warp

    const float NEG_INF = -__int_as_float(0x7f800000);
    float gm0 = NEG_INF, gm1 = NEG_INF;
    int   gc0 = 0, gc1 = 0;

    // This thread scans chunks [h*32, h*32+32) = samples [h*512, h*512+512)
    const int ch0 = h * CH_PER_THREAD;
    for (int ci = 0; ci < CH_PER_THREAD; ci++) {
        const int ch = ch0 + ci;
        float m0 = NEG_INF, m1 = NEG_INF;
        const float4* cbase = &tab[ch * CHUNK];
        #pragma unroll
        for (int t = 0; t < CHUNK; t++) {
            float4 s = cbase[t];                       // one LDS.128 per sample
            unsigned long long a = score2(u, vh, pack2(s.x), pack2(s.y),
                                                 pack2(s.z), pack2(s.w));
            m0 = fmaxf(m0, lo2(a));
            m1 = fmaxf(m1, hi2(a));
        }
        // Strict '>' keeps the earliest chunk on ties (first-index semantics)
        if (m0 > gm0) { gm0 = m0; gc0 = ch; }
        if (m1 > gm1) { gm1 = m1; gc1 = ch; }
    }

    // Merge the two halves across the thread pair (xor-1 shuffle).
    // On equal max, smaller chunk id wins -> global first-index semantics.
    {
        float pm0 = __shfl_xor_sync(0xFFFFFFFFu, gm0, 1);
        int   pc0 = __shfl_xor_sync(0xFFFFFFFFu, gc0, 1);
        if (pm0 > gm0 || (pm0 == gm0 && pc0 < gc0)) { gm0 = pm0; gc0 = pc0; }
        float pm1 = __shfl_xor_sync(0xFFFFFFFFu, gm1, 1);
        int   pc1 = __shfl_xor_sync(0xFFFFFFFFu, gc1, 1);
        if (pm1 > gm1 || (pm1 == gm1 && pc1 < gc1)) { gm1 = pm1; gc1 = pc1; }
    }

    // Parallel rescan: even thread resolves lane 0 (q0), odd resolves lane 1 (q1).
    // Coefficients bit-identical in both threads -> exact recompute.
    const int   ca = h ? gc1 : gc0;
    const float ta = h ? gm1 : gm0;
    int r = rescan_chunk(tab, u, vh, ca, ta, h);
    int pr = __shfl_xor_sync(0xFFFFFFFFu, r, 1);

    if (h != 0) return;   // odd thread done; even thread writes

    const int bidx0 = r;    // q0 (lane 0, resolved by this thread)
    const int bidx1 = pr;   // q1 (lane 1, resolved by partner)

    {
        float4 s0 = tab[bidx0];
        float4 s1 = tab[bidx1];
        const int obase = bl * 256 + j;
        *reinterpret_cast<float2*>(out + ZHAT_OFF + obase +   0) = make_float2(s0.x, s1.x);
        *reinterpret_cast<float2*>(out + ZHAT_OFF + obase +  64) = make_float2(s0.y, s1.y);
        *reinterpret_cast<float2*>(out + ZHAT_OFF + obase + 128) = make_float2(s0.z, s1.z);
        *reinterpret_cast<float2*>(out + ZHAT_OFF + obase + 192) = make_float2(s0.w, s1.w);
        if (out_size >= FULL_OUT) {
            *reinterpret_cast<float2*>(out + IDX_OFF + k0) =
                make_float2((float)bidx0, (float)bidx1);
        }
    }
}

extern "C" void kernel_launch(void* const* d_in, const int* in_sizes, int n_in,
                              void* d_out, int out_size) {
    const float* z     = (const float*)d_in[0];
    const float* eps   = (const float*)d_in[1];
    const float* prior = (const float*)d_in[2];
    (void)in_sizes; (void)n_in;
    const int thread_slots = (NQ / QPT) * SPLIT;               // 262144
    const int blocks = (thread_slots + THREADS - 1) / THREADS; // 586 -> 4 CTAs/SM
    gq_kernel<<<blocks, THREADS>>>(z, eps, prior, (float*)d_out, out_size);
}

// round 16
// speedup vs baseline: 1.0589x; 1.0373x over previous
#include <cuda_runtime.h>
#include <math.h>

// Problem constants (fixed shapes from reference)
#define NQ      262144      // total queries = B*L*cg = 4*1024*64
#define NSAM    1024        // prior samples
#define THREADS 448
#define QPT     4           // queries per warp-pair lane (2 f32x2 lane-packs)
#define CHUNK   16          // samples per argmax chunk
#define NCHUNK  (NSAM / CHUNK)          // 64 total
#define CH_PER_WARP (NCHUNK / 2)        // 32 per warp of the pair
#define PAIRS_PER_BLOCK (THREADS / 64)  // 7 warp-pairs per block
#define NQUAD   (NQ / QPT)              // 65536 query-quads
#define ZHAT_OFF   0
#define NOQ_OFF    1048576  // B*L*C
#define IDX_OFF    2097152  // 2*B*L*C
#define FULL_OUT   2359296  // + B*L*cg

// ---- packed f32x2 helpers (Blackwell FFMA2/FMUL2) ----
__device__ __forceinline__ unsigned long long ffma2(unsigned long long a,
                                                    unsigned long long b,
                                                    unsigned long long c) {
    unsigned long long d;
    asm("fma.rn.f32x2 %0, %1, %2, %3;" : "=l"(d) : "l"(a), "l"(b), "l"(c));
    return d;
}
__device__ __forceinline__ unsigned long long fmul2(unsigned long long a,
                                                    unsigned long long b) {
    unsigned long long d;
    asm("mul.rn.f32x2 %0, %1, %2;" : "=l"(d) : "l"(a), "l"(b));
    return d;
}
__device__ __forceinline__ unsigned long long pack2(float x) {     // (x, x)
    unsigned long long r;
    asm("mov.b64 %0, {%1, %1};" : "=l"(r) : "f"(x));
    return r;
}
__device__ __forceinline__ unsigned long long packxy(float lo, float hi) {  // (lo, hi)
    unsigned long long r;
    asm("mov.b64 %0, {%1, %2};" : "=l"(r) : "f"(lo), "f"(hi));
    return r;
}
__device__ __forceinline__ float lo2(unsigned long long a) {
    return __uint_as_float((unsigned)(a & 0xffffffffull));
}
__device__ __forceinline__ float hi2(unsigned long long a) {
    return __uint_as_float((unsigned)(a >> 32));
}

// Packed score of TWO queries (in lanes) against ONE sample.
// Main loop and rescan share this sequence -> bit-identical recompute.
__device__ __forceinline__ unsigned long long score2(
        const unsigned long long* u, const unsigned long long* vh,
        unsigned long long s0, unsigned long long s1,
        unsigned long long s2, unsigned long long s3) {
    unsigned long long t, a;
    t = ffma2(vh[0], s0, u[0]);  a = fmul2(s0, t);
    t = ffma2(vh[1], s1, u[1]);  a = ffma2(s1, t, a);
    t = ffma2(vh[2], s2, u[2]);  a = ffma2(s2, t, a);
    t = ffma2(vh[3], s3, u[3]);  a = ffma2(s3, t, a);
    return a;
}

// Recompute one chunk for one lane-pack; return smallest sample index whose
// selected lane equals target exactly.
__device__ __forceinline__ int rescan_chunk(const float4* __restrict__ tab,
                                            const unsigned long long* u,
                                            const unsigned long long* vh,
                                            int chunk, float target, int odd) {
    int found = NSAM;
    #pragma unroll 4
    for (int t = 0; t < CHUNK; t++) {
        int n = chunk * CHUNK + t;
        float4 s = tab[n];
        unsigned long long a = score2(u, vh, pack2(s.x), pack2(s.y),
                                             pack2(s.z), pack2(s.w));
        float v = odd ? hi2(a) : lo2(a);
        if (v == target) found = min(found, n);
    }
    return found;
}

__global__ void __launch_bounds__(THREADS, 2)
gq_kernel(const float* __restrict__ z,
          const float* __restrict__ eps,
          const float* __restrict__ prior,
          float* __restrict__ out,
          int out_size)
{
    // Sample table = raw prior rows. All 32 lanes of a warp read the SAME
    // address in the main loop -> perfect broadcast, 1 wavefront per LDS.128.
    __shared__ __align__(16) float4 tab[NSAM];        // 16 KB
    __shared__ float mbuf[THREADS * 4];               // merge: maxes
    __shared__ int   cbuf[THREADS * 4];               // merge: chunk ids
    __shared__ int   rbuf[THREADS * 2];               // rescan result exchange

    const int tid  = threadIdx.x;
    const int wid  = tid >> 5;
    const int lane = tid & 31;
    const int h    = wid & 1;          // which sample half this WARP scans

    for (int n = tid; n < NSAM; n += THREADS)
        tab[n] = reinterpret_cast<const float4*>(prior)[n];

    // Warp pair (2w, 2w+1) owns 32 query-quads; lane = one quad.
    const int pairg = blockIdx.x * PAIRS_PER_BLOCK + (wid >> 1);
    const int quad  = pairg * 32 + lane;
    const bool valid = (quad < NQUAD);
    const int kq = valid ? quad : (NQUAD - 1);        // clamp for safe loads
    const int k0 = kq * QPT;
    const int bl = k0 >> 6;     // (b*L + l)
    const int j  = k0 & 63;

    // Lane-packed per-query coefficients (identical in both warps of a pair)
    unsigned long long u01[4], u23[4], vh01[4], vh23[4];

    #pragma unroll
    for (int g = 0; g < 4; g++) {
        const int moff = bl * 512 + g * 64 + j;           // mu
        float4 mu4 = *reinterpret_cast<const float4*>(z + moff);
        float4 lv4 = *reinterpret_cast<const float4*>(z + moff + 256);
        lv4.x = fminf(fmaxf(lv4.x, -30.0f), 20.0f);
        lv4.y = fminf(fmaxf(lv4.y, -30.0f), 20.0f);
        lv4.z = fminf(fmaxf(lv4.z, -30.0f), 20.0f);
        lv4.w = fminf(fmaxf(lv4.w, -30.0f), 20.0f);
        float ivx = expf(-lv4.x), ivy = expf(-lv4.y);
        float ivz = expf(-lv4.z), ivw = expf(-lv4.w);
        u01[g]  = packxy(mu4.x * ivx, mu4.y * ivy);
        u23[g]  = packxy(mu4.z * ivz, mu4.w * ivw);
        vh01[g] = packxy(0.5f * (1.0f - ivx), 0.5f * (1.0f - ivy));
        vh23[g] = packxy(0.5f * (1.0f - ivz), 0.5f * (1.0f - ivw));

        // Fused zhat_noquant (written once per quad, by the even warp)
        if (h == 0 && valid && out_size >= IDX_OFF) {
            const int eoff = bl * 256 + g * 64 + j;
            float4 e4 = *reinterpret_cast<const float4*>(eps + eoff);
            float4 nq;
            nq.x = fmaf(e4.x, expf(0.5f * lv4.x), mu4.x);
            nq.y = fmaf(e4.y, expf(0.5f * lv4.y), mu4.y);
            nq.z = fmaf(e4.z, expf(0.5f * lv4.z), mu4.z);
            nq.w = fmaf(e4.w, expf(0.5f * lv4.w), mu4.w);
            *reinterpret_cast<float4*>(out + NOQ_OFF + eoff) = nq;
        }
    }
    __syncthreads();   // tab ready (ALL threads reach: no early returns)

    const float NEG_INF = -__int_as_float(0x7f800000);
    float gm[QPT];
    int   gc[QPT];
    #pragma unroll
    for (int q = 0; q < QPT; q++) { gm[q] = NEG_INF; gc[q] = 0; }

    // This warp scans chunks [h*32, h*32+32); tab addresses depend only on
    // h and loop counters -> warp-uniform -> broadcast LDS.
    const int ch0 = h * CH_PER_WARP;
    for (int ci = 0; ci < CH_PER_WARP; ci++) {
        const int ch = ch0 + ci;
        float m0 = NEG_INF, m1 = NEG_INF, m2 = NEG_INF, m3 = NEG_INF;
        const float4* cbase = &tab[ch * CHUNK];
        #pragma unroll
        for (int t = 0; t < CHUNK; t++) {
            float4 s = cbase[t];                       // broadcast LDS.128
            unsigned long long s0 = pack2(s.x), s1 = pack2(s.y);
            unsigned long long s2 = pack2(s.z), s3 = pack2(s.w);
            unsigned long long a01 = score2(u01, vh01, s0, s1, s2, s3);
            unsigned long long a23 = score2(u23, vh23, s0, s1, s2, s3);
            m0 = fmaxf(m0, lo2(a01));
            m1 = fmaxf(m1, hi2(a01));
            m2 = fmaxf(m2, lo2(a23));
            m3 = fmaxf(m3, hi2(a23));
        }
        // Strict '>' keeps the earliest chunk on ties (first-index semantics)
        if (m0 > gm[0]) { gm[0] = m0; gc[0] = ch; }
        if (m1 > gm[1]) { gm[1] = m1; gc[1] = ch; }
        if (m2 > gm[2]) { gm[2] = m2; gc[2] = ch; }
        if (m3 > gm[3]) { gm[3] = m3; gc[3] = ch; }
    }

    // Merge halves across the warp pair via smem (partner thread = tid ^ 32).
    #pragma unroll
    for (int q = 0; q < QPT; q++) { mbuf[tid * 4 + q] = gm[q]; cbuf[tid * 4 + q] = gc[q]; }
    __syncthreads();
    const int ptid = tid ^ 32;
    #pragma unroll
    for (int q = 0; q < QPT; q++) {
        float pm = mbuf[ptid * 4 + q];
        int   pc = cbuf[ptid * 4 + q];
        // On equal max, smaller chunk id wins -> global first-index semantics
        if (pm > gm[q] || (pm == gm[q] && pc < gc[q])) { gm[q] = pm; gc[q] = pc; }
    }

    // Parallel rescan: even warp resolves q0,q1; odd warp q2,q3 (coefficients
    // bit-identical in both warps of the pair).
    unsigned long long ua[4], va[4];
    #pragma unroll
    for (int g = 0; g < 4; g++) {
        ua[g] = h ? u23[g]  : u01[g];
        va[g] = h ? vh23[g] : vh01[g];
    }
    const int   ca0 = h ? gc[2] : gc[0];
    const int   ca1 = h ? gc[3] : gc[1];
    const float ta0 = h ? gm[2] : gm[0];
    const float ta1 = h ? gm[3] : gm[1];
    int ra = rescan_chunk(tab, ua, va, ca0, ta0, 0);
    int rb = rescan_chunk(tab, ua, va, ca1, ta1, 1);

    rbuf[tid * 2]     = ra;
    rbuf[tid * 2 + 1] = rb;
    __syncthreads();

    if (h != 0 || !valid) return;   // all barriers done; safe to exit

    int bidx[QPT];
    bidx[0] = ra;
    bidx[1] = rb;
    bidx[2] = rbuf[ptid * 2];
    bidx[3] = rbuf[ptid * 2 + 1];

    {
        // Gather winning prior rows from the smem table
        float r[QPT][4];
        #pragma unroll
        for (int q = 0; q < QPT; q++) {
            float4 s = tab[bidx[q]];
            r[q][0] = s.x; r[q][1] = s.y; r[q][2] = s.z; r[q][3] = s.w;
        }
        const int obase = bl * 256 + j;
        #pragma unroll
        for (int g = 0; g < 4; g++) {
            float4 o4 = make_float4(r[0][g], r[1][g], r[2][g], r[3][g]);
            *reinterpret_cast<float4*>(out + ZHAT_OFF + obase + g * 64) = o4;
        }
        if (out_size >= FULL_OUT) {
            float4 i4 = make_float4((float)bidx[0], (float)bidx[1],
                                    (float)bidx[2], (float)bidx[3]);
            *reinterpret_cast<float4*>(out + IDX_OFF + k0) = i4;
        }
    }
}

extern "C" void kernel_launch(void* const* d_in, const int* in_sizes, int n_in,
                              void* d_out, int out_size) {
    const float* z     = (const float*)d_in[0];
    const float* eps   = (const float*)d_in[1];
    const float* prior = (const float*)d_in[2];
    (void)in_sizes; (void)n_in;
    const int pairs  = NQUAD / 32;                         // 2048 warp-pairs
    const int blocks = (pairs + PAIRS_PER_BLOCK - 1) / PAIRS_PER_BLOCK;  // 293
    gq_kernel<<<blocks, THREADS>>>(z, eps, prior, (float*)d_out, out_size);
}